// round 16
// baseline (speedup 1.0000x reference)
#include <cuda_runtime.h>
#include <cuda_fp16.h>
#include <cstdint>

#define D 128
#define MAXN 50000
#define ETILE 128   // edge kernel tile
#define NTILE 64    // node kernel tile

// ---------------- device scratch (allocation-free rule) ----------------
__device__ float g_agg[MAXN * D];
__device__ float g_num[MAXN * 3];
__device__ float g_cnt[MAXN];
__device__ float g_U[MAXN * D];
__device__ float g_V[MAXN * D];
__device__ int   g_is64;
// fp16 weight images, XOR-swizzled [n][k] (256B rows):
// 0=We2, 1=Wx1, 2=We1top, 3=We1bot, 4=Wh1top, 5=Wh1bot, 6=Wh2
__device__ unsigned short g_B[7 * 16384];

__device__ __forceinline__ float silu_f(float v) {
    return v * (1.0f / (1.0f + __expf(-v)));
}
__device__ __forceinline__ uint32_t smem_u32(const void* p) {
    uint32_t a;
    asm("{ .reg .u64 t; cvta.to.shared.u64 t, %1; cvt.u32.u64 %0, t; }"
        : "=r"(a) : "l"(p));
    return a;
}
__device__ __forceinline__ void red_add_f4(float* ptr, float4 v) {
    asm volatile("red.global.add.v4.f32 [%0], {%1, %2, %3, %4};"
                 :: "l"(ptr), "f"(v.x), "f"(v.y), "f"(v.z), "f"(v.w)
                 : "memory");
}

#define LDSM_X4(r, addr)                                                        \
    asm volatile("ldmatrix.sync.aligned.m8n8.x4.shared.b16 {%0,%1,%2,%3}, [%4];"\
        : "=r"((r)[0]), "=r"((r)[1]), "=r"((r)[2]), "=r"((r)[3]) : "r"(addr))

#define MMA_F16(d, a, b0, b1)                                                   \
    asm volatile("mma.sync.aligned.m16n8k16.row.col.f32.f16.f16.f32 "           \
        "{%0,%1,%2,%3}, {%4,%5,%6,%7}, {%8,%9}, {%0,%1,%2,%3};"                 \
        : "+f"((d)[0]), "+f"((d)[1]), "+f"((d)[2]), "+f"((d)[3])                \
        : "r"((a)[0]), "r"((a)[1]), "r"((a)[2]), "r"((a)[3]), "r"(b0), "r"(b1))

__device__ __forceinline__ void split2h(float v0, float v1, uint32_t& hi, uint32_t& lo) {
    __half2 h = __floats2half2_rn(v0, v1);
    float2 hf = __half22float2(h);
    __half2 l = __floats2half2_rn(v0 - hf.x, v1 - hf.y);
    hi = *reinterpret_cast<uint32_t*>(&h);
    lo = *reinterpret_cast<uint32_t*>(&l);
}
__device__ __forceinline__ float hlo16(uint32_t u) {
    return __half2float(__ushort_as_half((unsigned short)(u & 0xffff)));
}
__device__ __forceinline__ float hhi16(uint32_t u) {
    return __half2float(__ushort_as_half((unsigned short)(u >> 16)));
}

// ---------------- misc small kernels ----------------
__global__ void detect_kernel(const void* eidx_raw, int E, int Nn) {
    const long long* p = (const long long*)eidx_raw;
    int ok = 1;
    for (int i = 0; i < 64 && i < E; i++) {
        long long v = p[i];
        if (v < 0 || v >= (long long)Nn) { ok = 0; break; }
    }
    g_is64 = ok;
}
__device__ __forceinline__ int load_idx(const void* eidx_raw, long long pos, int is64) {
    if (is64) return (int)((const long long*)eidx_raw)[pos];
    return ((const int*)eidx_raw)[pos];
}

__global__ void prep_weights_kernel(const float* __restrict__ We2,
                                    const float* __restrict__ Wx1,
                                    const float* __restrict__ We1,
                                    const float* __restrict__ Wh1,
                                    const float* __restrict__ Wh2) {
    int idx = blockIdx.x * blockDim.x + threadIdx.x;
    if (idx >= 7 * 16384) return;
    int m = idx >> 14;
    int e = idx & 16383;
    int n = e >> 7;
    int k = e & 127;
    float v;
    switch (m) {
        case 0: v = We2[k * D + n]; break;
        case 1: v = Wx1[k * D + n]; break;
        case 2: v = We1[k * D + n]; break;
        case 3: v = We1[(128 + k) * D + n]; break;
        case 4: v = Wh1[k * D + n]; break;
        case 5: v = Wh1[(128 + k) * D + n]; break;
        default: v = Wh2[k * D + n]; break;
    }
    int off = n * 256 + (((k >> 3) ^ (n & 15)) << 4) + (k & 7) * 2;
    g_B[m * 16384 + (off >> 1)] = __half_as_ushort(__float2half_rn(v));
}

// ---------------- GEMM cores ----------------
// 16-row variants (node-side kernels)
__device__ __forceinline__ void gemm_acc16(
    uint32_t aHi, uint32_t aLo, uint32_t bB,
    int lane, int m0, int nb, float acc[8][4])
{
    const int arow_l = lane & 15;
    const int akh    = lane >> 4;
    const int brow_l = ((lane >> 4) & 1) * 8 + (lane & 7);
    const int bkh    = (lane >> 3) & 1;

    #pragma unroll 1
    for (int kb = 0; kb < 8; kb++) {
        uint32_t ah[4], al[4], bh[4][4];
        {
            int row = m0 + arow_l;
            int ch  = kb * 2 + akh;
            uint32_t off = row * 256 + ((ch ^ (row & 15)) << 4);
            LDSM_X4(ah, aHi + off);
            LDSM_X4(al, aLo + off);
        }
        #pragma unroll
        for (int p = 0; p < 4; p++) {
            int row = nb + p * 16 + brow_l;
            int ch  = kb * 2 + bkh;
            uint32_t off = row * 256 + ((ch ^ (row & 15)) << 4);
            LDSM_X4(bh[p], bB + off);
        }
        #pragma unroll
        for (int na = 0; na < 8; na++) {
            uint32_t b0 = bh[na >> 1][(na & 1) * 2];
            uint32_t b1 = bh[na >> 1][(na & 1) * 2 + 1];
            MMA_F16(acc[na], ah, b0, b1);
            MMA_F16(acc[na], al, b0, b1);
        }
    }
}
__device__ __forceinline__ void gemm_tile16(
    uint32_t aHi, uint32_t aLo, uint32_t bB,
    int lane, int m0, int nb, float acc[8][4])
{
    #pragma unroll
    for (int na = 0; na < 8; na++)
        #pragma unroll
        for (int q = 0; q < 4; q++) acc[na][q] = 0.f;
    gemm_acc16(aHi, aLo, bB, lane, m0, nb, acc);
}

// 32-row variants (edge kernel, warp tile 32x64)
__device__ __forceinline__ void gemm_tile32(
    uint32_t aHi, uint32_t aLo, uint32_t bB,
    int lane, int m0, int nb, float acc[2][8][4])
{
    #pragma unroll
    for (int ma = 0; ma < 2; ma++)
        #pragma unroll
        for (int na = 0; na < 8; na++)
            #pragma unroll
            for (int q = 0; q < 4; q++) acc[ma][na][q] = 0.f;

    const int arow_l = lane & 15;
    const int akh    = lane >> 4;
    const int brow_l = ((lane >> 4) & 1) * 8 + (lane & 7);
    const int bkh    = (lane >> 3) & 1;

    #pragma unroll 1
    for (int kb = 0; kb < 8; kb++) {
        uint32_t ah[2][4], al[2][4], bh[4][4];
        #pragma unroll
        for (int ma = 0; ma < 2; ma++) {
            int row = m0 + ma * 16 + arow_l;
            int ch  = kb * 2 + akh;
            uint32_t off = row * 256 + ((ch ^ (row & 15)) << 4);
            LDSM_X4(ah[ma], aHi + off);
            LDSM_X4(al[ma], aLo + off);
        }
        #pragma unroll
        for (int p = 0; p < 4; p++) {
            int row = nb + p * 16 + brow_l;
            int ch  = kb * 2 + bkh;
            uint32_t off = row * 256 + ((ch ^ (row & 15)) << 4);
            LDSM_X4(bh[p], bB + off);
        }
        #pragma unroll
        for (int ma = 0; ma < 2; ma++)
            #pragma unroll
            for (int na = 0; na < 8; na++) {
                uint32_t b0 = bh[na >> 1][(na & 1) * 2];
                uint32_t b1 = bh[na >> 1][(na & 1) * 2 + 1];
                MMA_F16(acc[ma][na], ah[ma], b0, b1);
                MMA_F16(acc[ma][na], al[ma], b0, b1);
            }
    }
}
__device__ __forceinline__ void gemm_tile32_1c(
    uint32_t aHi, uint32_t bB,
    int lane, int m0, int nb, float acc[2][8][4])
{
    #pragma unroll
    for (int ma = 0; ma < 2; ma++)
        #pragma unroll
        for (int na = 0; na < 8; na++)
            #pragma unroll
            for (int q = 0; q < 4; q++) acc[ma][na][q] = 0.f;

    const int arow_l = lane & 15;
    const int akh    = lane >> 4;
    const int brow_l = ((lane >> 4) & 1) * 8 + (lane & 7);
    const int bkh    = (lane >> 3) & 1;

    #pragma unroll 1
    for (int kb = 0; kb < 8; kb++) {
        uint32_t ah[2][4], bh[4][4];
        #pragma unroll
        for (int ma = 0; ma < 2; ma++) {
            int row = m0 + ma * 16 + arow_l;
            int ch  = kb * 2 + akh;
            uint32_t off = row * 256 + ((ch ^ (row & 15)) << 4);
            LDSM_X4(ah[ma], aHi + off);
        }
        #pragma unroll
        for (int p = 0; p < 4; p++) {
            int row = nb + p * 16 + brow_l;
            int ch  = kb * 2 + bkh;
            uint32_t off = row * 256 + ((ch ^ (row & 15)) << 4);
            LDSM_X4(bh[p], bB + off);
        }
        #pragma unroll
        for (int ma = 0; ma < 2; ma++)
            #pragma unroll
            for (int na = 0; na < 8; na++) {
                uint32_t b0 = bh[na >> 1][(na & 1) * 2];
                uint32_t b1 = bh[na >> 1][(na & 1) * 2 + 1];
                MMA_F16(acc[ma][na], ah[ma], b0, b1);
            }
    }
}

// ---------------- edge kernel SMEM (bytes), ETILE=128, 2 CTAs/SM ----------------
#define SM_W    0        // 32768 rotating weight image
#define SM_AHI  32768    // 32768 (128 rows x 256B); head doubles as WGEO
#define SM_ALO  65536    // 32768
#define SM_GEO  98304    // 128*13 f32 = 6656
#define SM_DST  104960   // 128 int
#define SM_SRC  105472   // 128 int
#define SM_BE2  105984   // 128 f32
#define SM_BX1  106496
#define SM_WX2  107008
#define SM_PPART 107520  // 2*128 f32
#define SM_BX2  108544
#define SM_TOTAL 108560

__global__ __launch_bounds__(256, 2) void edge_mma_kernel(
    const float* __restrict__ x, const float* __restrict__ vel,
    const void* __restrict__ eidx_raw, const float* __restrict__ We1,
    const float* __restrict__ be2, const float* __restrict__ bx1,
    const float* __restrict__ Wx2, const float* __restrict__ bx2,
    float* __restrict__ out_m, int E)
{
    extern __shared__ char smem[];
    float* smf = (float*)smem;
    const uint32_t sb = smem_u32(smem);
    const int tid  = threadIdx.x;
    const int warp = tid >> 5;
    const int lane = tid & 31;
    const int m0   = (warp & 3) * 32;   // GEMM row block (32 rows)
    const int nb   = (warp >> 2) * 64;  // GEMM col block
    const int rw0  = warp * 16;         // scalar phase: warp owns 16 edge rows
    const int c0   = lane * 4;
    const int is64 = g_is64;

    if (tid < 128) {
        smf[(SM_BE2 >> 2) + tid] = be2[tid];
        smf[(SM_BX1 >> 2) + tid] = bx1[tid];
        smf[(SM_WX2 >> 2) + tid] = Wx2[tid];
    }
    if (tid == 0) smf[SM_BX2 >> 2] = bx2[0];
    __syncthreads();

    float* geo_sf = smf + (SM_GEO >> 2);
    float* wgeo   = smf + (SM_AHI >> 2);
    int*   dst_s  = (int*)(smem + SM_DST);
    int*   src_s  = (int*)(smem + SM_SRC);
    float* ppart  = smf + (SM_PPART >> 2);
    const uint4* gB = (const uint4*)g_B;

    const int ntiles = (E + ETILE - 1) / ETILE;

    for (int tile = blockIdx.x; tile < ntiles; tile += gridDim.x) {
        const int ebase = tile * ETILE;

        // ===== stage: indices + geometry (tid<128, edge = tid); copy WGEO =====
        float relx = 0.f, rely = 0.f, relz = 0.f;
        int dreg = 0; bool vreg = false;
        if (tid < ETILE) {
            int eg = ebase + tid;
            vreg = (eg < E);
            int ec = vreg ? eg : 0;
            int s = load_idx(eidx_raw, ec, is64);
            int d = load_idx(eidx_raw, (long long)E + ec, is64);
            src_s[tid] = s; dst_s[tid] = d; dreg = d;
            float rx = x[s*3+0] - x[d*3+0];
            float ry = x[s*3+1] - x[d*3+1];
            float rz = x[s*3+2] - x[d*3+2];
            relx = rx; rely = ry; relz = rz;
            float d2 = rx*rx + ry*ry + rz*rz;
            float dist = fmaxf(sqrtf(d2), 1e-8f);
            float inv = 1.0f / dist;
            float ux = rx*inv, uy = ry*inv, uz = rz*inv;
            geo_sf[tid * 13 + 0] = d2;
            #pragma unroll
            for (int j = 0; j < 5; j++) {
                const float* vs = vel + (size_t)s * 15 + j * 3;
                const float* vd = vel + (size_t)d * 15 + j * 3;
                geo_sf[tid * 13 + 1 + j] = vs[0]*ux + vs[1]*uy + vs[2]*uz;
                geo_sf[tid * 13 + 6 + j] = vd[0]*ux + vd[1]*uy + vd[2]*uz;
            }
        }
        {
            const float4* src = (const float4*)(We1 + 256 * D);
            float4* dst = (float4*)wgeo;
            for (int i = tid; i < 352; i += 256) dst[i] = src[i];
        }
        __syncthreads();

        // ===== scalar phase: 16 rows per warp, 4 cols per lane =====
        float z[16][4];
        {
            #pragma unroll
            for (int i = 0; i < 16; i++) {
                int s2  = src_s[rw0 + i];
                int d2i = dst_s[rw0 + i];
                float4 u = *(const float4*)(g_U + (size_t)s2 * D + c0);
                float4 v = *(const float4*)(g_V + (size_t)d2i * D + c0);
                z[i][0] = u.x + v.x; z[i][1] = u.y + v.y;
                z[i][2] = u.z + v.z; z[i][3] = u.w + v.w;
            }
            #pragma unroll 1
            for (int k = 0; k < 11; k++) {
                float4 w = *(const float4*)(wgeo + k * D + c0);
                #pragma unroll
                for (int i = 0; i < 16; i++) {
                    float f = geo_sf[(rw0 + i) * 13 + k];
                    z[i][0] = fmaf(f, w.x, z[i][0]);
                    z[i][1] = fmaf(f, w.y, z[i][1]);
                    z[i][2] = fmaf(f, w.z, z[i][2]);
                    z[i][3] = fmaf(f, w.w, z[i][3]);
                }
            }
        }
        __syncthreads();   // all WGEO reads done before A stores clobber it

        // ===== store A hi/lo; fill W = We2 =====
        {
            const int chunk = c0 >> 3;
            const int sub   = (c0 & 7) * 2;
            #pragma unroll
            for (int i = 0; i < 16; i++) {
                int r = rw0 + i;
                float v0 = silu_f(z[i][0]), v1 = silu_f(z[i][1]);
                float v2 = silu_f(z[i][2]), v3 = silu_f(z[i][3]);
                uint32_t h0, l0, h1, l1;
                split2h(v0, v1, h0, l0);
                split2h(v2, v3, h1, l1);
                uint32_t off = r * 256 + ((chunk ^ (r & 15)) << 4) + sub;
                *(uint2*)(smem + SM_AHI + off) = make_uint2(h0, h1);
                *(uint2*)(smem + SM_ALO + off) = make_uint2(l0, l1);
            }
            for (int i = tid; i < 2048; i += 256)
                ((uint4*)(smem + SM_W))[i] = gB[i];
        }
        __syncthreads();

        // ===== GEMM1: y1 @ We2 (2-chain) =====
        float acc[2][8][4];
        gemm_tile32(sb + SM_AHI, sb + SM_ALO, sb + SM_W, lane, m0, nb, acc);
        __syncthreads();

        // epilogue1: m = silu(acc + be2) -> A; fill W = Wx1
        #pragma unroll
        for (int ma = 0; ma < 2; ma++)
            #pragma unroll
            for (int na = 0; na < 8; na++) {
                int col = nb + na * 8 + (lane & 3) * 2;
                float b0 = smf[(SM_BE2 >> 2) + col];
                float b1 = smf[(SM_BE2 >> 2) + col + 1];
                int rA = m0 + ma * 16 + (lane >> 2);
                int rB = rA + 8;
                float v0 = silu_f(acc[ma][na][0] + b0);
                float v1 = silu_f(acc[ma][na][1] + b1);
                float v2 = silu_f(acc[ma][na][2] + b0);
                float v3 = silu_f(acc[ma][na][3] + b1);
                uint32_t hA, lA, hB, lB;
                split2h(v0, v1, hA, lA);
                split2h(v2, v3, hB, lB);
                uint32_t offA = rA * 256 + (((col >> 3) ^ (rA & 15)) << 4) + (col & 7) * 2;
                uint32_t offB = rB * 256 + (((col >> 3) ^ (rB & 15)) << 4) + (col & 7) * 2;
                *(uint32_t*)(smem + SM_AHI + offA) = hA;
                *(uint32_t*)(smem + SM_ALO + offA) = lA;
                *(uint32_t*)(smem + SM_AHI + offB) = hB;
                *(uint32_t*)(smem + SM_ALO + offB) = lB;
            }
        for (int i = tid; i < 2048; i += 256)
            ((uint4*)(smem + SM_W))[i] = gB[2048 + i];
        __syncthreads();

        // ===== GEMM2: m @ Wx1 (1-chain) =====
        gemm_tile32_1c(sb + SM_AHI, sb + SM_W, lane, m0, nb, acc);

        // out_m + agg vector-red from A buffers (m = hi + lo)
        #pragma unroll 1
        for (int i = 0; i < 16; i++) {
            int row = warp * 16 + i;
            int eg = ebase + row;
            if (eg < E) {
                uint32_t off = row * 256 + ((((lane >> 1) ^ (row & 15))) << 4)
                             + (lane & 1) * 8;
                uint2 uh = *(const uint2*)(smem + SM_AHI + off);
                uint2 ul = *(const uint2*)(smem + SM_ALO + off);
                float4 f;
                f.x = hlo16(uh.x) + hlo16(ul.x);
                f.y = hhi16(uh.x) + hhi16(ul.x);
                f.z = hlo16(uh.y) + hlo16(ul.y);
                f.w = hhi16(uh.y) + hhi16(ul.y);
                *(float4*)(out_m + (size_t)eg * D + lane * 4) = f;
                red_add_f4(g_agg + (size_t)dst_s[row] * D + lane * 4, f);
            }
        }

        // phi_x tail: p_row = sum_col silu(acc2 + bx1)*wx2
        {
            float ps[2][2] = {{0.f, 0.f}, {0.f, 0.f}};
            #pragma unroll
            for (int ma = 0; ma < 2; ma++)
                #pragma unroll
                for (int na = 0; na < 8; na++) {
                    int col = nb + na * 8 + (lane & 3) * 2;
                    float b0 = smf[(SM_BX1 >> 2) + col];
                    float b1 = smf[(SM_BX1 >> 2) + col + 1];
                    float w0 = smf[(SM_WX2 >> 2) + col];
                    float w1 = smf[(SM_WX2 >> 2) + col + 1];
                    ps[ma][0] += silu_f(acc[ma][na][0] + b0) * w0
                               + silu_f(acc[ma][na][1] + b1) * w1;
                    ps[ma][1] += silu_f(acc[ma][na][2] + b0) * w0
                               + silu_f(acc[ma][na][3] + b1) * w1;
                }
            #pragma unroll
            for (int ma = 0; ma < 2; ma++)
                #pragma unroll
                for (int q = 0; q < 2; q++) {
                    ps[ma][q] += __shfl_xor_sync(0xffffffffu, ps[ma][q], 1);
                    ps[ma][q] += __shfl_xor_sync(0xffffffffu, ps[ma][q], 2);
                }
            if ((lane & 3) == 0) {
                int base = (warp >> 2) * 128;
                #pragma unroll
                for (int ma = 0; ma < 2; ma++) {
                    int rA = m0 + ma * 16 + (lane >> 2);
                    ppart[base + rA]     = ps[ma][0];
                    ppart[base + rA + 8] = ps[ma][1];
                }
            }
        }
        __syncthreads();

        if (tid < ETILE && vreg) {
            float p = ppart[tid] + ppart[128 + tid] + smf[SM_BX2 >> 2];
            atomicAdd(&g_num[dreg*3 + 0], relx * p);
            atomicAdd(&g_num[dreg*3 + 1], rely * p);
            atomicAdd(&g_num[dreg*3 + 2], relz * p);
            atomicAdd(&g_cnt[dreg], 1.0f);
        }
        __syncthreads();
    }
}

// ---------------- node-side HMMA kernels (unchanged from R15, NTILE=64) ------
#define SMN_W    0
#define SMN_AHI  32768
#define SMN_ALO  49152
#define SMN_S1   65536
#define SMN_S2   66048
#define SMN_TOTAL 66560

__device__ __forceinline__ void stage_split(
    char* smem, const float* __restrict__ src, int nbase, int Nn,
    int rw0, int c0)
{
    const int chunk = c0 >> 3;
    const int sub   = (c0 & 7) * 2;
    #pragma unroll
    for (int i = 0; i < 8; i++) {
        int r = rw0 + i;
        int n = nbase + r;
        int nc = (n < Nn) ? n : 0;
        float4 hv = *(const float4*)(src + (size_t)nc * D + c0);
        uint32_t h0, l0, h1, l1;
        split2h(hv.x, hv.y, h0, l0);
        split2h(hv.z, hv.w, h1, l1);
        uint32_t off = r * 256 + ((chunk ^ (r & 15)) << 4) + sub;
        *(uint2*)(smem + SMN_AHI + off) = make_uint2(h0, h1);
        *(uint2*)(smem + SMN_ALO + off) = make_uint2(l0, l1);
    }
}

__global__ __launch_bounds__(256, 3) void precompute_mma_kernel(
    const float* __restrict__ h, const float* __restrict__ be1, int Nn)
{
    extern __shared__ char smem[];
    const uint32_t sb = smem_u32(smem);
    const int tid  = threadIdx.x;
    const int warp = tid >> 5;
    const int lane = tid & 31;
    const int m0   = (warp & 3) * 16;
    const int nb   = (warp >> 2) * 64;
    const int rw0  = warp * 8;
    const int c0   = lane * 4;
    const int nbase = blockIdx.x * NTILE;
    const uint4* gB = (const uint4*)g_B;

    stage_split(smem, h, nbase, Nn, rw0, c0);
    for (int i = tid; i < 2048; i += 256)
        ((uint4*)(smem + SMN_W))[i] = gB[2 * 2048 + i];
    {
        float4 z4 = make_float4(0.f, 0.f, 0.f, 0.f);
        for (int i = tid; i < 64 * 32; i += 256) {
            int r = i >> 5;
            int n = nbase + r;
            if (n < Nn)
                ((float4*)(g_agg + (size_t)n * D))[i & 31] = z4;
        }
        if (tid < NTILE) {
            int n = nbase + tid;
            if (n < Nn) {
                g_num[n*3+0] = 0.f; g_num[n*3+1] = 0.f; g_num[n*3+2] = 0.f;
                g_cnt[n] = 0.f;
            }
        }
    }
    __syncthreads();

    float acc[8][4];
    const int colb = nb + (lane & 3) * 2;
    const int rA = m0 + (lane >> 2);
    const int rB = rA + 8;

    #pragma unroll
    for (int na = 0; na < 8; na++) {
        int col = colb + na * 8;
        float b0 = be1[col], b1 = be1[col + 1];
        acc[na][0] = b0; acc[na][1] = b1; acc[na][2] = b0; acc[na][3] = b1;
    }
    gemm_acc16(sb + SMN_AHI, sb + SMN_ALO, sb + SMN_W, lane, m0, nb, acc);
    #pragma unroll
    for (int na = 0; na < 8; na++) {
        int col = colb + na * 8;
        if (nbase + rA < Nn)
            *(float2*)(g_U + (size_t)(nbase + rA) * D + col) =
                make_float2(acc[na][0], acc[na][1]);
        if (nbase + rB < Nn)
            *(float2*)(g_U + (size_t)(nbase + rB) * D + col) =
                make_float2(acc[na][2], acc[na][3]);
    }
    __syncthreads();
    for (int i = tid; i < 2048; i += 256)
        ((uint4*)(smem + SMN_W))[i] = gB[3 * 2048 + i];
    __syncthreads();

    gemm_tile16(sb + SMN_AHI, sb + SMN_ALO, sb + SMN_W, lane, m0, nb, acc);
    #pragma unroll
    for (int na = 0; na < 8; na++) {
        int col = colb + na * 8;
        if (nbase + rA < Nn)
            *(float2*)(g_V + (size_t)(nbase + rA) * D + col) =
                make_float2(acc[na][0], acc[na][1]);
        if (nbase + rB < Nn)
            *(float2*)(g_V + (size_t)(nbase + rB) * D + col) =
                make_float2(acc[na][2], acc[na][3]);
    }
}

__global__ __launch_bounds__(256, 3) void node_mma_kernel(
    const float* __restrict__ h, const float* __restrict__ x,
    const float* __restrict__ bh1, const float* __restrict__ bh2,
    const float* __restrict__ gamma, const float* __restrict__ beta,
    float* __restrict__ out_h, float* __restrict__ out_x, int Nn)
{
    extern __shared__ char smem[];
    float* smf = (float*)smem;
    const uint32_t sb = smem_u32(smem);
    const int tid  = threadIdx.x;
    const int warp = tid >> 5;
    const int lane = tid & 31;
    const int m0   = (warp & 3) * 16;
    const int nb   = (warp >> 2) * 64;
    const int rw0  = warp * 8;
    const int c0   = lane * 4;
    const int nbase = blockIdx.x * NTILE;
    const uint4* gB = (const uint4*)g_B;
    const int wg = warp >> 2;

    stage_split(smem, h, nbase, Nn, rw0, c0);
    for (int i = tid; i < 2048; i += 256)
        ((uint4*)(smem + SMN_W))[i] = gB[4 * 2048 + i];
    __syncthreads();

    float acc[8][4];
    const int colb = nb + (lane & 3) * 2;
    const int rA = m0 + (lane >> 2);
    const int rB = rA + 8;
    const int nA = nbase + rA;
    const int nB = nbase + rB;
    const int nAc = (nA < Nn) ? nA : 0;
    const int nBc = (nB < Nn) ? nB : 0;

    #pragma unroll
    for (int na = 0; na < 8; na++) {
        int col = colb + na * 8;
        float b0 = bh1[col], b1 = bh1[col + 1];
        acc[na][0] = b0; acc[na][1] = b1; acc[na][2] = b0; acc[na][3] = b1;
    }
    gemm_acc16(sb + SMN_AHI, sb + SMN_ALO, sb + SMN_W, lane, m0, nb, acc);
    __syncthreads();

    stage_split(smem, g_agg, nbase, Nn, rw0, c0);
    for (int i = tid; i < 2048; i += 256)
        ((uint4*)(smem + SMN_W))[i] = gB[5 * 2048 + i];
    __syncthreads();

    gemm_acc16(sb + SMN_AHI, sb + SMN_ALO, sb + SMN_W, lane, m0, nb, acc);
    __syncthreads();

    #pragma unroll
    for (int na = 0; na < 8; na++) {
        int col = colb + na * 8;
        float v0 = silu_f(acc[na][0]);
        float v1 = silu_f(acc[na][1]);
        float v2 = silu_f(acc[na][2]);
        float v3 = silu_f(acc[na][3]);
        uint32_t hA, lA, hB, lB;
        split2h(v0, v1, hA, lA);
        split2h(v2, v3, hB, lB);
        uint32_t offA = rA * 256 + (((col >> 3) ^ (rA & 15)) << 4) + (col & 7) * 2;
        uint32_t offB = rB * 256 + (((col >> 3) ^ (rB & 15)) << 4) + (col & 7) * 2;
        *(uint32_t*)(smem + SMN_AHI + offA) = hA;
        *(uint32_t*)(smem + SMN_ALO + offA) = lA;
        *(uint32_t*)(smem + SMN_AHI + offB) = hB;
        *(uint32_t*)(smem + SMN_ALO + offB) = lB;
    }
    for (int i = tid; i < 2048; i += 256)
        ((uint4*)(smem + SMN_W))[i] = gB[6 * 2048 + i];
    __syncthreads();

    #pragma unroll
    for (int na = 0; na < 8; na++) {
        int col = colb + na * 8;
        float b0 = bh2[col], b1 = bh2[col + 1];
        acc[na][0] = b0; acc[na][1] = b1; acc[na][2] = b0; acc[na][3] = b1;
    }
    gemm_acc16(sb + SMN_AHI, sb + SMN_ALO, sb + SMN_W, lane, m0, nb, acc);

    float hv[8][4];
    float s1A = 0.f, s2A = 0.f, s1B = 0.f, s2B = 0.f;
    #pragma unroll
    for (int na = 0; na < 8; na++) {
        int col = colb + na * 8;
        float2 ha = *(const float2*)(h + (size_t)nAc * D + col);
        float2 hb = *(const float2*)(h + (size_t)nBc * D + col);
        hv[na][0] = ha.x + acc[na][0];
        hv[na][1] = ha.y + acc[na][1];
        hv[na][2] = hb.x + acc[na][2];
        hv[na][3] = hb.y + acc[na][3];
        s1A += hv[na][0] + hv[na][1];
        s2A += hv[na][0]*hv[na][0] + hv[na][1]*hv[na][1];
        s1B += hv[na][2] + hv[na][3];
        s2B += hv[na][2]*hv[na][2] + hv[na][3]*hv[na][3];
    }
    s1A += __shfl_xor_sync(0xffffffffu, s1A, 1);
    s1A += __shfl_xor_sync(0xffffffffu, s1A, 2);
    s2A += __shfl_xor_sync(0xffffffffu, s2A, 1);
    s2A += __shfl_xor_sync(0xffffffffu, s2A, 2);
    s1B += __shfl_xor_sync(0xffffffffu, s1B, 1);
    s1B += __shfl_xor_sync(0xffffffffu, s1B, 2);
    s2B += __shfl_xor_sync(0xffffffffu, s2B, 1);
    s2B += __shfl_xor_sync(0xffffffffu, s2B, 2);

    float* s1buf = smf + (SMN_S1 >> 2);
    float* s2buf = smf + (SMN_S2 >> 2);
    if ((lane & 3) == 0) {
        s1buf[wg * 64 + rA] = s1A;
        s1buf[wg * 64 + rB] = s1B;
        s2buf[wg * 64 + rA] = s2A;
        s2buf[wg * 64 + rB] = s2B;
    }
    __syncthreads();

    float s1t = s1buf[rA] + s1buf[64 + rA];
    float s2t = s2buf[rA] + s2buf[64 + rA];
    float muA = s1t * (1.0f / 128.0f);
    float rsA = rsqrtf(s2t * (1.0f / 128.0f) - muA * muA + 1e-5f);
    s1t = s1buf[rB] + s1buf[64 + rB];
    s2t = s2buf[rB] + s2buf[64 + rB];
    float muB = s1t * (1.0f / 128.0f);
    float rsB = rsqrtf(s2t * (1.0f / 128.0f) - muB * muB + 1e-5f);

    #pragma unroll
    for (int na = 0; na < 8; na++) {
        int col = colb + na * 8;
        float g0 = gamma[col], g1 = gamma[col + 1];
        float b0 = beta[col],  b1 = beta[col + 1];
        if (nA < Nn)
            *(float2*)(out_h + (size_t)nA * D + col) =
                make_float2((hv[na][0] - muA) * rsA * g0 + b0,
                            (hv[na][1] - muA) * rsA * g1 + b1);
        if (nB < Nn)
            *(float2*)(out_h + (size_t)nB * D + col) =
                make_float2((hv[na][2] - muB) * rsB * g0 + b0,
                            (hv[na][3] - muB) * rsB * g1 + b1);
    }

    if (tid < NTILE) {
        int n = nbase + tid;
        if (n < Nn) {
            float cnt = g_cnt[n];
            float inv = 1.0f / fmaxf(cnt, 1.0f);
            out_x[n*3 + 0] = x[n*3 + 0] + g_num[n*3 + 0] * inv;
            out_x[n*3 + 1] = x[n*3 + 1] + g_num[n*3 + 1] * inv;
            out_x[n*3 + 2] = x[n*3 + 2] + g_num[n*3 + 2] * inv;
        }
    }
}

extern "C" void kernel_launch(void* const* d_in, const int* in_sizes, int n_in,
                              void* d_out, int out_size) {
    const float* h    = (const float*)d_in[0];
    const float* x    = (const float*)d_in[1];
    const float* vel  = (const float*)d_in[2];
    const void*  eidx = d_in[3];
    const float* We1 = (const float*)d_in[4],  *be1 = (const float*)d_in[5];
    const float* We2 = (const float*)d_in[6],  *be2 = (const float*)d_in[7];
    const float* Wx1 = (const float*)d_in[8],  *bx1 = (const float*)d_in[9];
    const float* Wx2 = (const float*)d_in[10], *bx2 = (const float*)d_in[11];
    const float* Wh1 = (const float*)d_in[12], *bh1 = (const float*)d_in[13];
    const float* Wh2 = (const float*)d_in[14], *bh2 = (const float*)d_in[15];
    const float* gamma = (const float*)d_in[16], *beta = (const float*)d_in[17];

    int Nn = in_sizes[0] / D;
    int E  = in_sizes[3] / 2;

    float* out   = (float*)d_out;
    float* out_h = out;
    float* out_x = out + (size_t)Nn * D;
    float* out_m = out_x + (size_t)Nn * 3;

    static int smem_set = 0;
    if (!smem_set) {
        cudaFuncSetAttribute(edge_mma_kernel,
                             cudaFuncAttributeMaxDynamicSharedMemorySize, SM_TOTAL);
        cudaFuncSetAttribute(precompute_mma_kernel,
                             cudaFuncAttributeMaxDynamicSharedMemorySize, SMN_TOTAL);
        cudaFuncSetAttribute(node_mma_kernel,
                             cudaFuncAttributeMaxDynamicSharedMemorySize, SMN_TOTAL);
        smem_set = 1;
    }

    int ntile_n = (Nn + NTILE - 1) / NTILE;

    detect_kernel<<<1, 1>>>(eidx, E, Nn);
    prep_weights_kernel<<<(7 * 16384 + 255) / 256, 256>>>(We2, Wx1, We1, Wh1, Wh2);
    precompute_mma_kernel<<<ntile_n, 256, SMN_TOTAL>>>(h, be1, Nn);
    edge_mma_kernel<<<296, 256, SM_TOTAL>>>(x, vel, eidx, We1,
                                            be2, bx1, Wx2, bx2, out_m, E);
    node_mma_kernel<<<ntile_n, 256, SMN_TOTAL>>>(h, x, bh1, bh2,
                                                 gamma, beta, out_h, out_x, Nn);
}

// round 17
// speedup vs baseline: 1.1372x; 1.1372x over previous
#include <cuda_runtime.h>
#include <cuda_fp16.h>
#include <cstdint>

#define D 128
#define MAXN 50000
#define TILE_M 64

// ---------------- device scratch (allocation-free rule) ----------------
__device__ float g_agg[MAXN * D];
__device__ float g_num[MAXN * 3];
__device__ float g_cnt[MAXN];
__device__ float g_U[MAXN * D];
__device__ float g_V[MAXN * D];
__device__ int   g_is64;
// fp16 weight images, XOR-swizzled [n][k] (256B rows):
// 0=We2, 1=Wx1, 2=We1top, 3=We1bot, 4=Wh1top, 5=Wh1bot, 6=Wh2
__device__ unsigned short g_B[7 * 16384];

__device__ __forceinline__ float silu_f(float v) {
    return v * (1.0f / (1.0f + __expf(-v)));
}
__device__ __forceinline__ uint32_t smem_u32(const void* p) {
    uint32_t a;
    asm("{ .reg .u64 t; cvta.to.shared.u64 t, %1; cvt.u32.u64 %0, t; }"
        : "=r"(a) : "l"(p));
    return a;
}
__device__ __forceinline__ void red_add_f4(float* ptr, float4 v) {
    asm volatile("red.global.add.v4.f32 [%0], {%1, %2, %3, %4};"
                 :: "l"(ptr), "f"(v.x), "f"(v.y), "f"(v.z), "f"(v.w)
                 : "memory");
}
__device__ __forceinline__ void cp_async16(uint32_t saddr, const void* gaddr) {
    asm volatile("cp.async.cg.shared.global [%0], [%1], 16;"
                 :: "r"(saddr), "l"(gaddr) : "memory");
}
#define CP_COMMIT() asm volatile("cp.async.commit_group;" ::: "memory")
#define CP_WAIT0()  asm volatile("cp.async.wait_group 0;" ::: "memory")

#define LDSM_X4(r, addr)                                                        \
    asm volatile("ldmatrix.sync.aligned.m8n8.x4.shared.b16 {%0,%1,%2,%3}, [%4];"\
        : "=r"((r)[0]), "=r"((r)[1]), "=r"((r)[2]), "=r"((r)[3]) : "r"(addr))

#define MMA_F16(d, a, b0, b1)                                                   \
    asm volatile("mma.sync.aligned.m16n8k16.row.col.f32.f16.f16.f32 "           \
        "{%0,%1,%2,%3}, {%4,%5,%6,%7}, {%8,%9}, {%0,%1,%2,%3};"                 \
        : "+f"((d)[0]), "+f"((d)[1]), "+f"((d)[2]), "+f"((d)[3])                \
        : "r"((a)[0]), "r"((a)[1]), "r"((a)[2]), "r"((a)[3]), "r"(b0), "r"(b1))

__device__ __forceinline__ void split2h(float v0, float v1, uint32_t& hi, uint32_t& lo) {
    __half2 h = __floats2half2_rn(v0, v1);
    float2 hf = __half22float2(h);
    __half2 l = __floats2half2_rn(v0 - hf.x, v1 - hf.y);
    hi = *reinterpret_cast<uint32_t*>(&h);
    lo = *reinterpret_cast<uint32_t*>(&l);
}
__device__ __forceinline__ float hlo16(uint32_t u) {
    return __half2float(__ushort_as_half((unsigned short)(u & 0xffff)));
}
__device__ __forceinline__ float hhi16(uint32_t u) {
    return __half2float(__ushort_as_half((unsigned short)(u >> 16)));
}

// ---------------- misc small kernels ----------------
__global__ void detect_kernel(const void* eidx_raw, int E, int Nn) {
    const long long* p = (const long long*)eidx_raw;
    int ok = 1;
    for (int i = 0; i < 64 && i < E; i++) {
        long long v = p[i];
        if (v < 0 || v >= (long long)Nn) { ok = 0; break; }
    }
    g_is64 = ok;
}
__device__ __forceinline__ int load_idx(const void* eidx_raw, long long pos, int is64) {
    if (is64) return (int)((const long long*)eidx_raw)[pos];
    return ((const int*)eidx_raw)[pos];
}

__global__ void prep_weights_kernel(const float* __restrict__ We2,
                                    const float* __restrict__ Wx1,
                                    const float* __restrict__ We1,
                                    const float* __restrict__ Wh1,
                                    const float* __restrict__ Wh2) {
    int idx = blockIdx.x * blockDim.x + threadIdx.x;
    if (idx >= 7 * 16384) return;
    int m = idx >> 14;
    int e = idx & 16383;
    int n = e >> 7;
    int k = e & 127;
    float v;
    switch (m) {
        case 0: v = We2[k * D + n]; break;
        case 1: v = Wx1[k * D + n]; break;
        case 2: v = We1[k * D + n]; break;
        case 3: v = We1[(128 + k) * D + n]; break;
        case 4: v = Wh1[k * D + n]; break;
        case 5: v = Wh1[(128 + k) * D + n]; break;
        default: v = Wh2[k * D + n]; break;
    }
    int off = n * 256 + (((k >> 3) ^ (n & 15)) << 4) + (k & 7) * 2;
    g_B[m * 16384 + (off >> 1)] = __half_as_ushort(__float2half_rn(v));
}

// ---------------- GEMM cores (16-row warp tile) ----------------
__device__ __forceinline__ void gemm_acc16(
    uint32_t aHi, uint32_t aLo, uint32_t bB,
    int lane, int m0, int nb, float acc[8][4])
{
    const int arow_l = lane & 15;
    const int akh    = lane >> 4;
    const int brow_l = ((lane >> 4) & 1) * 8 + (lane & 7);
    const int bkh    = (lane >> 3) & 1;

    #pragma unroll 1
    for (int kb = 0; kb < 8; kb++) {
        uint32_t ah[4], al[4], bh[4][4];
        {
            int row = m0 + arow_l;
            int ch  = kb * 2 + akh;
            uint32_t off = row * 256 + ((ch ^ (row & 15)) << 4);
            LDSM_X4(ah, aHi + off);
            LDSM_X4(al, aLo + off);
        }
        #pragma unroll
        for (int p = 0; p < 4; p++) {
            int row = nb + p * 16 + brow_l;
            int ch  = kb * 2 + bkh;
            uint32_t off = row * 256 + ((ch ^ (row & 15)) << 4);
            LDSM_X4(bh[p], bB + off);
        }
        #pragma unroll
        for (int na = 0; na < 8; na++) {
            uint32_t b0 = bh[na >> 1][(na & 1) * 2];
            uint32_t b1 = bh[na >> 1][(na & 1) * 2 + 1];
            MMA_F16(acc[na], ah, b0, b1);
            MMA_F16(acc[na], al, b0, b1);
        }
    }
}
__device__ __forceinline__ void gemm_tile16(
    uint32_t aHi, uint32_t aLo, uint32_t bB,
    int lane, int m0, int nb, float acc[8][4])
{
    #pragma unroll
    for (int na = 0; na < 8; na++)
        #pragma unroll
        for (int q = 0; q < 4; q++) acc[na][q] = 0.f;
    gemm_acc16(aHi, aLo, bB, lane, m0, nb, acc);
}
__device__ __forceinline__ void gemm_tile16_1c(
    uint32_t aHi, uint32_t bB,
    int lane, int m0, int nb, float acc[8][4])
{
    #pragma unroll
    for (int na = 0; na < 8; na++)
        #pragma unroll
        for (int q = 0; q < 4; q++) acc[na][q] = 0.f;

    const int arow_l = lane & 15;
    const int akh    = lane >> 4;
    const int brow_l = ((lane >> 4) & 1) * 8 + (lane & 7);
    const int bkh    = (lane >> 3) & 1;

    #pragma unroll 1
    for (int kb = 0; kb < 8; kb++) {
        uint32_t ah[4], bh[4][4];
        {
            int row = m0 + arow_l;
            int ch  = kb * 2 + akh;
            uint32_t off = row * 256 + ((ch ^ (row & 15)) << 4);
            LDSM_X4(ah, aHi + off);
        }
        #pragma unroll
        for (int p = 0; p < 4; p++) {
            int row = nb + p * 16 + brow_l;
            int ch  = kb * 2 + bkh;
            uint32_t off = row * 256 + ((ch ^ (row & 15)) << 4);
            LDSM_X4(bh[p], bB + off);
        }
        #pragma unroll
        for (int na = 0; na < 8; na++) {
            uint32_t b0 = bh[na >> 1][(na & 1) * 2];
            uint32_t b1 = bh[na >> 1][(na & 1) * 2 + 1];
            MMA_F16(acc[na], ah, b0, b1);
        }
    }
}

// ---------------- edge kernel SMEM (bytes), TILE 64, 3 CTAs/SM ----------------
#define SM_W    0
#define SM_AHI  32768
#define SM_ALO  49152
#define SM_GEO  65536
#define SM_DST  68864
#define SM_SRC  69120
#define SM_BE2  69376
#define SM_BX1  69888
#define SM_WX2  70400
#define SM_PPART 70912
#define SM_BX2  71424
#define SM_TOTAL 71440

__global__ __launch_bounds__(256, 3) void edge_mma_kernel(
    const float* __restrict__ x, const float* __restrict__ vel,
    const void* __restrict__ eidx_raw, const float* __restrict__ We1,
    const float* __restrict__ be2, const float* __restrict__ bx1,
    const float* __restrict__ Wx2, const float* __restrict__ bx2,
    float* __restrict__ out_m, int E)
{
    extern __shared__ char smem[];
    float* smf = (float*)smem;
    const uint32_t sb = smem_u32(smem);
    const int tid  = threadIdx.x;
    const int warp = tid >> 5;
    const int lane = tid & 31;
    const int m0   = (warp & 3) * 16;
    const int nb   = (warp >> 2) * 64;
    const int rw0  = warp * 8;
    const int c0   = lane * 4;
    const int is64 = g_is64;

    if (tid < 128) {
        smf[(SM_BE2 >> 2) + tid] = be2[tid];
        smf[(SM_BX1 >> 2) + tid] = bx1[tid];
        smf[(SM_WX2 >> 2) + tid] = Wx2[tid];
    }
    if (tid == 0) smf[SM_BX2 >> 2] = bx2[0];
    __syncthreads();

    float* geo_sf = smf + (SM_GEO >> 2);
    float* wgeo   = smf + (SM_AHI >> 2);
    int*   dst_s  = (int*)(smem + SM_DST);
    int*   src_s  = (int*)(smem + SM_SRC);
    float* ppart  = smf + (SM_PPART >> 2);
    const uint4* gB = (const uint4*)g_B;

    const int ntiles = (E + TILE_M - 1) / TILE_M;

    for (int tile = blockIdx.x; tile < ntiles; tile += gridDim.x) {
        const int ebase = tile * TILE_M;

        // ===== stage: indices + geometry (tid<64); copy WGEO into A head =====
        float relx = 0.f, rely = 0.f, relz = 0.f;
        int dreg = 0; bool vreg = false;
        if (tid < TILE_M) {
            int eg = ebase + tid;
            vreg = (eg < E);
            int ec = vreg ? eg : 0;
            int s = load_idx(eidx_raw, ec, is64);
            int d = load_idx(eidx_raw, (long long)E + ec, is64);
            src_s[tid] = s; dst_s[tid] = d; dreg = d;
            float rx = x[s*3+0] - x[d*3+0];
            float ry = x[s*3+1] - x[d*3+1];
            float rz = x[s*3+2] - x[d*3+2];
            relx = rx; rely = ry; relz = rz;
            float d2 = rx*rx + ry*ry + rz*rz;
            float dist = fmaxf(sqrtf(d2), 1e-8f);
            float inv = 1.0f / dist;
            float ux = rx*inv, uy = ry*inv, uz = rz*inv;
            geo_sf[tid * 13 + 0] = d2;
            #pragma unroll
            for (int j = 0; j < 5; j++) {
                const float* vs = vel + (size_t)s * 15 + j * 3;
                const float* vd = vel + (size_t)d * 15 + j * 3;
                geo_sf[tid * 13 + 1 + j] = vs[0]*ux + vs[1]*uy + vs[2]*uz;
                geo_sf[tid * 13 + 6 + j] = vd[0]*ux + vd[1]*uy + vd[2]*uz;
            }
        }
        {
            const float4* src = (const float4*)(We1 + 256 * D);
            float4* dst = (float4*)wgeo;
            for (int i = tid; i < 352; i += 256) dst[i] = src[i];
        }
        __syncthreads();

        // ===== scalar phase (column-mapped, coalesced gathers) =====
        float z[8][4];
        {
            #pragma unroll
            for (int i = 0; i < 8; i++) {
                int s2  = src_s[rw0 + i];
                int d2i = dst_s[rw0 + i];
                float4 u = *(const float4*)(g_U + (size_t)s2 * D + c0);
                float4 v = *(const float4*)(g_V + (size_t)d2i * D + c0);
                z[i][0] = u.x + v.x; z[i][1] = u.y + v.y;
                z[i][2] = u.z + v.z; z[i][3] = u.w + v.w;
            }
            #pragma unroll 1
            for (int k = 0; k < 11; k++) {
                float4 w = *(const float4*)(wgeo + k * D + c0);
                #pragma unroll
                for (int i = 0; i < 8; i++) {
                    float f = geo_sf[(rw0 + i) * 13 + k];
                    z[i][0] = fmaf(f, w.x, z[i][0]);
                    z[i][1] = fmaf(f, w.y, z[i][1]);
                    z[i][2] = fmaf(f, w.z, z[i][2]);
                    z[i][3] = fmaf(f, w.w, z[i][3]);
                }
            }
        }
        __syncthreads();   // WGEO reads done before A stores clobber it

        // ===== async-fill W = We2; store A hi/lo meanwhile =====
        for (int i = tid; i < 2048; i += 256)
            cp_async16(sb + SM_W + i * 16, gB + i);
        CP_COMMIT();
        {
            const int chunk = c0 >> 3;
            const int sub   = (c0 & 7) * 2;
            #pragma unroll
            for (int i = 0; i < 8; i++) {
                int r = rw0 + i;
                float v0 = silu_f(z[i][0]), v1 = silu_f(z[i][1]);
                float v2 = silu_f(z[i][2]), v3 = silu_f(z[i][3]);
                uint32_t h0, l0, h1, l1;
                split2h(v0, v1, h0, l0);
                split2h(v2, v3, h1, l1);
                uint32_t off = r * 256 + ((chunk ^ (r & 15)) << 4) + sub;
                *(uint2*)(smem + SM_AHI + off) = make_uint2(h0, h1);
                *(uint2*)(smem + SM_ALO + off) = make_uint2(l0, l1);
            }
        }
        CP_WAIT0();
        __syncthreads();

        // ===== GEMM1: y1 @ We2 (2-chain) =====
        float acc[8][4];
        gemm_tile16(sb + SM_AHI, sb + SM_ALO, sb + SM_W, lane, m0, nb, acc);
        __syncthreads();

        // ===== async-fill W = Wx1; epilogue1 meanwhile =====
        for (int i = tid; i < 2048; i += 256)
            cp_async16(sb + SM_W + i * 16, gB + 2048 + i);
        CP_COMMIT();
        #pragma unroll
        for (int na = 0; na < 8; na++) {
            int col = nb + na * 8 + (lane & 3) * 2;
            float b0 = smf[(SM_BE2 >> 2) + col];
            float b1 = smf[(SM_BE2 >> 2) + col + 1];
            int rA = m0 + (lane >> 2);
            int rB = rA + 8;
            float v0 = silu_f(acc[na][0] + b0);
            float v1 = silu_f(acc[na][1] + b1);
            float v2 = silu_f(acc[na][2] + b0);
            float v3 = silu_f(acc[na][3] + b1);
            uint32_t hA, lA, hB, lB;
            split2h(v0, v1, hA, lA);
            split2h(v2, v3, hB, lB);
            uint32_t offA = rA * 256 + (((col >> 3) ^ (rA & 15)) << 4) + (col & 7) * 2;
            uint32_t offB = rB * 256 + (((col >> 3) ^ (rB & 15)) << 4) + (col & 7) * 2;
            *(uint32_t*)(smem + SM_AHI + offA) = hA;
            *(uint32_t*)(smem + SM_ALO + offA) = lA;
            *(uint32_t*)(smem + SM_AHI + offB) = hB;
            *(uint32_t*)(smem + SM_ALO + offB) = lB;
        }
        CP_WAIT0();
        __syncthreads();

        // ===== GEMM2: m @ Wx1 (1-chain) =====
        gemm_tile16_1c(sb + SM_AHI, sb + SM_W, lane, m0, nb, acc);

        // out_m + agg vector-red from A buffers (m = hi + lo)
        #pragma unroll 1
        for (int i = 0; i < 8; i++) {
            int row = warp * 8 + i;
            int eg = ebase + row;
            if (eg < E) {
                uint32_t off = row * 256 + ((((lane >> 1) ^ (row & 15))) << 4)
                             + (lane & 1) * 8;
                uint2 uh = *(const uint2*)(smem + SM_AHI + off);
                uint2 ul = *(const uint2*)(smem + SM_ALO + off);
                float4 f;
                f.x = hlo16(uh.x) + hlo16(ul.x);
                f.y = hhi16(uh.x) + hhi16(ul.x);
                f.z = hlo16(uh.y) + hlo16(ul.y);
                f.w = hhi16(uh.y) + hhi16(ul.y);
                *(float4*)(out_m + (size_t)eg * D + lane * 4) = f;
                red_add_f4(g_agg + (size_t)dst_s[row] * D + lane * 4, f);
            }
        }

        // phi_x tail
        {
            float ps[2] = {0.f, 0.f};
            #pragma unroll
            for (int na = 0; na < 8; na++) {
                int col = nb + na * 8 + (lane & 3) * 2;
                float b0 = smf[(SM_BX1 >> 2) + col];
                float b1 = smf[(SM_BX1 >> 2) + col + 1];
                float w0 = smf[(SM_WX2 >> 2) + col];
                float w1 = smf[(SM_WX2 >> 2) + col + 1];
                ps[0] += silu_f(acc[na][0] + b0) * w0
                       + silu_f(acc[na][1] + b1) * w1;
                ps[1] += silu_f(acc[na][2] + b0) * w0
                       + silu_f(acc[na][3] + b1) * w1;
            }
            #pragma unroll
            for (int q = 0; q < 2; q++) {
                ps[q] += __shfl_xor_sync(0xffffffffu, ps[q], 1);
                ps[q] += __shfl_xor_sync(0xffffffffu, ps[q], 2);
            }
            if ((lane & 3) == 0) {
                int base = (warp >> 2) * 64;
                int rA = m0 + (lane >> 2);
                ppart[base + rA]     = ps[0];
                ppart[base + rA + 8] = ps[1];
            }
        }
        __syncthreads();

        if (tid < TILE_M && vreg) {
            float p = ppart[tid] + ppart[64 + tid] + smf[SM_BX2 >> 2];
            atomicAdd(&g_num[dreg*3 + 0], relx * p);
            atomicAdd(&g_num[dreg*3 + 1], rely * p);
            atomicAdd(&g_num[dreg*3 + 2], relz * p);
            atomicAdd(&g_cnt[dreg], 1.0f);
        }
        __syncthreads();
    }
}

// ---------------- node-side HMMA kernels ----------------
#define SMN_W    0
#define SMN_AHI  32768
#define SMN_ALO  49152
#define SMN_S1   65536
#define SMN_S2   66048
#define SMN_TOTAL 66560

__device__ __forceinline__ void stage_split(
    char* smem, const float* __restrict__ src, int nbase, int Nn,
    int rw0, int c0)
{
    const int chunk = c0 >> 3;
    const int sub   = (c0 & 7) * 2;
    #pragma unroll
    for (int i = 0; i < 8; i++) {
        int r = rw0 + i;
        int n = nbase + r;
        int nc = (n < Nn) ? n : 0;
        float4 hv = *(const float4*)(src + (size_t)nc * D + c0);
        uint32_t h0, l0, h1, l1;
        split2h(hv.x, hv.y, h0, l0);
        split2h(hv.z, hv.w, h1, l1);
        uint32_t off = r * 256 + ((chunk ^ (r & 15)) << 4) + sub;
        *(uint2*)(smem + SMN_AHI + off) = make_uint2(h0, h1);
        *(uint2*)(smem + SMN_ALO + off) = make_uint2(l0, l1);
    }
}

__global__ __launch_bounds__(256, 3) void precompute_mma_kernel(
    const float* __restrict__ h, const float* __restrict__ be1, int Nn)
{
    extern __shared__ char smem[];
    const uint32_t sb = smem_u32(smem);
    const int tid  = threadIdx.x;
    const int warp = tid >> 5;
    const int lane = tid & 31;
    const int m0   = (warp & 3) * 16;
    const int nb   = (warp >> 2) * 64;
    const int rw0  = warp * 8;
    const int c0   = lane * 4;
    const int nbase = blockIdx.x * TILE_M;
    const uint4* gB = (const uint4*)g_B;

    // async fill W = We1top; stage h + zero scratch meanwhile
    for (int i = tid; i < 2048; i += 256)
        cp_async16(sb + SMN_W + i * 16, gB + 2 * 2048 + i);
    CP_COMMIT();
    stage_split(smem, h, nbase, Nn, rw0, c0);
    {
        float4 z4 = make_float4(0.f, 0.f, 0.f, 0.f);
        for (int i = tid; i < 64 * 32; i += 256) {
            int r = i >> 5;
            int n = nbase + r;
            if (n < Nn)
                ((float4*)(g_agg + (size_t)n * D))[i & 31] = z4;
        }
        if (tid < TILE_M) {
            int n = nbase + tid;
            if (n < Nn) {
                g_num[n*3+0] = 0.f; g_num[n*3+1] = 0.f; g_num[n*3+2] = 0.f;
                g_cnt[n] = 0.f;
            }
        }
    }
    CP_WAIT0();
    __syncthreads();

    float acc[8][4];
    const int colb = nb + (lane & 3) * 2;
    const int rA = m0 + (lane >> 2);
    const int rB = rA + 8;

    #pragma unroll
    for (int na = 0; na < 8; na++) {
        int col = colb + na * 8;
        float b0 = be1[col], b1 = be1[col + 1];
        acc[na][0] = b0; acc[na][1] = b1; acc[na][2] = b0; acc[na][3] = b1;
    }
    gemm_acc16(sb + SMN_AHI, sb + SMN_ALO, sb + SMN_W, lane, m0, nb, acc);
    __syncthreads();   // W reads done
    for (int i = tid; i < 2048; i += 256)
        cp_async16(sb + SMN_W + i * 16, gB + 3 * 2048 + i);
    CP_COMMIT();
    #pragma unroll
    for (int na = 0; na < 8; na++) {
        int col = colb + na * 8;
        if (nbase + rA < Nn)
            *(float2*)(g_U + (size_t)(nbase + rA) * D + col) =
                make_float2(acc[na][0], acc[na][1]);
        if (nbase + rB < Nn)
            *(float2*)(g_U + (size_t)(nbase + rB) * D + col) =
                make_float2(acc[na][2], acc[na][3]);
    }
    CP_WAIT0();
    __syncthreads();

    gemm_tile16(sb + SMN_AHI, sb + SMN_ALO, sb + SMN_W, lane, m0, nb, acc);
    #pragma unroll
    for (int na = 0; na < 8; na++) {
        int col = colb + na * 8;
        if (nbase + rA < Nn)
            *(float2*)(g_V + (size_t)(nbase + rA) * D + col) =
                make_float2(acc[na][0], acc[na][1]);
        if (nbase + rB < Nn)
            *(float2*)(g_V + (size_t)(nbase + rB) * D + col) =
                make_float2(acc[na][2], acc[na][3]);
    }
}

__global__ __launch_bounds__(256, 3) void node_mma_kernel(
    const float* __restrict__ h, const float* __restrict__ x,
    const float* __restrict__ bh1, const float* __restrict__ bh2,
    const float* __restrict__ gamma, const float* __restrict__ beta,
    float* __restrict__ out_h, float* __restrict__ out_x, int Nn)
{
    extern __shared__ char smem[];
    float* smf = (float*)smem;
    const uint32_t sb = smem_u32(smem);
    const int tid  = threadIdx.x;
    const int warp = tid >> 5;
    const int lane = tid & 31;
    const int m0   = (warp & 3) * 16;
    const int nb   = (warp >> 2) * 64;
    const int rw0  = warp * 8;
    const int c0   = lane * 4;
    const int nbase = blockIdx.x * TILE_M;
    const uint4* gB = (const uint4*)g_B;
    const int wg = warp >> 2;

    for (int i = tid; i < 2048; i += 256)
        cp_async16(sb + SMN_W + i * 16, gB + 4 * 2048 + i);
    CP_COMMIT();
    stage_split(smem, h, nbase, Nn, rw0, c0);
    CP_WAIT0();
    __syncthreads();

    float acc[8][4];
    const int colb = nb + (lane & 3) * 2;
    const int rA = m0 + (lane >> 2);
    const int rB = rA + 8;
    const int nA = nbase + rA;
    const int nB = nbase + rB;
    const int nAc = (nA < Nn) ? nA : 0;
    const int nBc = (nB < Nn) ? nB : 0;

    #pragma unroll
    for (int na = 0; na < 8; na++) {
        int col = colb + na * 8;
        float b0 = bh1[col], b1 = bh1[col + 1];
        acc[na][0] = b0; acc[na][1] = b1; acc[na][2] = b0; acc[na][3] = b1;
    }
    gemm_acc16(sb + SMN_AHI, sb + SMN_ALO, sb + SMN_W, lane, m0, nb, acc);
    __syncthreads();

    for (int i = tid; i < 2048; i += 256)
        cp_async16(sb + SMN_W + i * 16, gB + 5 * 2048 + i);
    CP_COMMIT();
    stage_split(smem, g_agg, nbase, Nn, rw0, c0);
    CP_WAIT0();
    __syncthreads();

    gemm_acc16(sb + SMN_AHI, sb + SMN_ALO, sb + SMN_W, lane, m0, nb, acc);
    __syncthreads();

    for (int i = tid; i < 2048; i += 256)
        cp_async16(sb + SMN_W + i * 16, gB + 6 * 2048 + i);
    CP_COMMIT();
    #pragma unroll
    for (int na = 0; na < 8; na++) {
        int col = colb + na * 8;
        float v0 = silu_f(acc[na][0]);
        float v1 = silu_f(acc[na][1]);
        float v2 = silu_f(acc[na][2]);
        float v3 = silu_f(acc[na][3]);
        uint32_t hA, lA, hB, lB;
        split2h(v0, v1, hA, lA);
        split2h(v2, v3, hB, lB);
        uint32_t offA = rA * 256 + (((col >> 3) ^ (rA & 15)) << 4) + (col & 7) * 2;
        uint32_t offB = rB * 256 + (((col >> 3) ^ (rB & 15)) << 4) + (col & 7) * 2;
        *(uint32_t*)(smem + SMN_AHI + offA) = hA;
        *(uint32_t*)(smem + SMN_ALO + offA) = lA;
        *(uint32_t*)(smem + SMN_AHI + offB) = hB;
        *(uint32_t*)(smem + SMN_ALO + offB) = lB;
    }
    CP_WAIT0();
    __syncthreads();

    #pragma unroll
    for (int na = 0; na < 8; na++) {
        int col = colb + na * 8;
        float b0 = bh2[col], b1 = bh2[col + 1];
        acc[na][0] = b0; acc[na][1] = b1; acc[na][2] = b0; acc[na][3] = b1;
    }
    gemm_acc16(sb + SMN_AHI, sb + SMN_ALO, sb + SMN_W, lane, m0, nb, acc);

    float hv[8][4];
    float s1A = 0.f, s2A = 0.f, s1B = 0.f, s2B = 0.f;
    #pragma unroll
    for (int na = 0; na < 8; na++) {
        int col = colb + na * 8;
        float2 ha = *(const float2*)(h + (size_t)nAc * D + col);
        float2 hb = *(const float2*)(h + (size_t)nBc * D + col);
        hv[na][0] = ha.x + acc[na][0];
        hv[na][1] = ha.y + acc[na][1];
        hv[na][2] = hb.x + acc[na][2];
        hv[na][3] = hb.y + acc[na][3];
        s1A += hv[na][0] + hv[na][1];
        s2A += hv[na][0]*hv[na][0] + hv[na][1]*hv[na][1];
        s1B += hv[na][2] + hv[na][3];
        s2B += hv[na][2]*hv[na][2] + hv[na][3]*hv[na][3];
    }
    s1A += __shfl_xor_sync(0xffffffffu, s1A, 1);
    s1A += __shfl_xor_sync(0xffffffffu, s1A, 2);
    s2A += __shfl_xor_sync(0xffffffffu, s2A, 1);
    s2A += __shfl_xor_sync(0xffffffffu, s2A, 2);
    s1B += __shfl_xor_sync(0xffffffffu, s1B, 1);
    s1B += __shfl_xor_sync(0xffffffffu, s1B, 2);
    s2B += __shfl_xor_sync(0xffffffffu, s2B, 1);
    s2B += __shfl_xor_sync(0xffffffffu, s2B, 2);

    float* s1buf = smf + (SMN_S1 >> 2);
    float* s2buf = smf + (SMN_S2 >> 2);
    if ((lane & 3) == 0) {
        s1buf[wg * 64 + rA] = s1A;
        s1buf[wg * 64 + rB] = s1B;
        s2buf[wg * 64 + rA] = s2A;
        s2buf[wg * 64 + rB] = s2B;
    }
    __syncthreads();

    float s1t = s1buf[rA] + s1buf[64 + rA];
    float s2t = s2buf[rA] + s2buf[64 + rA];
    float muA = s1t * (1.0f / 128.0f);
    float rsA = rsqrtf(s2t * (1.0f / 128.0f) - muA * muA + 1e-5f);
    s1t = s1buf[rB] + s1buf[64 + rB];
    s2t = s2buf[rB] + s2buf[64 + rB];
    float muB = s1t * (1.0f / 128.0f);
    float rsB = rsqrtf(s2t * (1.0f / 128.0f) - muB * muB + 1e-5f);

    #pragma unroll
    for (int na = 0; na < 8; na++) {
        int col = colb + na * 8;
        float g0 = gamma[col], g1 = gamma[col + 1];
        float b0 = beta[col],  b1 = beta[col + 1];
        if (nA < Nn)
            *(float2*)(out_h + (size_t)nA * D + col) =
                make_float2((hv[na][0] - muA) * rsA * g0 + b0,
                            (hv[na][1] - muA) * rsA * g1 + b1);
        if (nB < Nn)
            *(float2*)(out_h + (size_t)nB * D + col) =
                make_float2((hv[na][2] - muB) * rsB * g0 + b0,
                            (hv[na][3] - muB) * rsB * g1 + b1);
    }

    if (tid < TILE_M) {
        int n = nbase + tid;
        if (n < Nn) {
            float cnt = g_cnt[n];
            float inv = 1.0f / fmaxf(cnt, 1.0f);
            out_x[n*3 + 0] = x[n*3 + 0] + g_num[n*3 + 0] * inv;
            out_x[n*3 + 1] = x[n*3 + 1] + g_num[n*3 + 1] * inv;
            out_x[n*3 + 2] = x[n*3 + 2] + g_num[n*3 + 2] * inv;
        }
    }
}

extern "C" void kernel_launch(void* const* d_in, const int* in_sizes, int n_in,
                              void* d_out, int out_size) {
    const float* h    = (const float*)d_in[0];
    const float* x    = (const float*)d_in[1];
    const float* vel  = (const float*)d_in[2];
    const void*  eidx = d_in[3];
    const float* We1 = (const float*)d_in[4],  *be1 = (const float*)d_in[5];
    const float* We2 = (const float*)d_in[6],  *be2 = (const float*)d_in[7];
    const float* Wx1 = (const float*)d_in[8],  *bx1 = (const float*)d_in[9];
    const float* Wx2 = (const float*)d_in[10], *bx2 = (const float*)d_in[11];
    const float* Wh1 = (const float*)d_in[12], *bh1 = (const float*)d_in[13];
    const float* Wh2 = (const float*)d_in[14], *bh2 = (const float*)d_in[15];
    const float* gamma = (const float*)d_in[16], *beta = (const float*)d_in[17];

    int Nn = in_sizes[0] / D;
    int E  = in_sizes[3] / 2;

    float* out   = (float*)d_out;
    float* out_h = out;
    float* out_x = out + (size_t)Nn * D;
    float* out_m = out_x + (size_t)Nn * 3;

    static int smem_set = 0;
    if (!smem_set) {
        cudaFuncSetAttribute(edge_mma_kernel,
                             cudaFuncAttributeMaxDynamicSharedMemorySize, SM_TOTAL);
        cudaFuncSetAttribute(precompute_mma_kernel,
                             cudaFuncAttributeMaxDynamicSharedMemorySize, SMN_TOTAL);
        cudaFuncSetAttribute(node_mma_kernel,
                             cudaFuncAttributeMaxDynamicSharedMemorySize, SMN_TOTAL);
        smem_set = 1;
    }

    int ntile_n = (Nn + TILE_M - 1) / TILE_M;

    detect_kernel<<<1, 1>>>(eidx, E, Nn);
    prep_weights_kernel<<<(7 * 16384 + 255) / 256, 256>>>(We2, Wx1, We1, Wh1, Wh2);
    precompute_mma_kernel<<<ntile_n, 256, SMN_TOTAL>>>(h, be1, Nn);
    edge_mma_kernel<<<444, 256, SM_TOTAL>>>(x, vel, eidx, We1,
                                            be2, bx1, Wx2, bx2, out_m, E);
    node_mma_kernel<<<ntile_n, 256, SMN_TOTAL>>>(h, x, bh1, bh2,
                                                 gamma, beta, out_h, out_x, Nn);
}